// round 11
// baseline (speedup 1.0000x reference)
#include <cuda_runtime.h>
#include <cstdint>

// DisulfideEnergy: bulk-async (UBLKCP) pipeline version.
//
// Output (single f32 buffer):
//   [0 .. 64000)              resi_energy (8,4,500,4)
//   [64000 .. 2064000)        atom_energy (500000,4)
//   [2064000 .. 6064000)      sulfur      (4000000) as 0.0/1.0

#define N_CHAINS   4
#define N_RES      500
#define SG_CODE    7
#define MAX_ATOMS  500000
#define MAX_WORDS  ((MAX_ATOMS + 31) / 32)        // 15625
#define PBLOCK     1024
#define TILE       1024                            // int4 pair-chunks per tile

// smem layout (bytes, all 16B aligned)
#define MASK_BYTES 62512                           // ((15625+3)&~3)*4
#define IN_OFF     MASK_BYTES                      // 2 x 16384
#define OUT_OFF    (IN_OFF + 2 * TILE * 16)        // 2 x 8192
#define MBAR_OFF   (OUT_OFF + 2 * TILE * 8)
#define SMEM_TOT   (MBAR_OFF + 64)

__device__ __align__(16) uint32_t g_sgmask[MAX_WORDS + 32];

// ---------------------------------------------------------------------------
// PTX helpers
// ---------------------------------------------------------------------------
__device__ __forceinline__ uint32_t smem_u32(const void* p)
{
    return (uint32_t)__cvta_generic_to_shared(p);
}
__device__ __forceinline__ void mbar_init(uint32_t mbar, uint32_t cnt)
{
    asm volatile("mbarrier.init.shared.b64 [%0], %1;" :: "r"(mbar), "r"(cnt)
                 : "memory");
}
__device__ __forceinline__ void mbar_expect_tx(uint32_t mbar, uint32_t bytes)
{
    asm volatile("mbarrier.arrive.expect_tx.shared.b64 _, [%0], %1;"
                 :: "r"(mbar), "r"(bytes) : "memory");
}
__device__ __forceinline__ void mbar_wait(uint32_t mbar, uint32_t parity)
{
    asm volatile(
        "{\n\t"
        ".reg .pred P1;\n\t"
        "WAIT_LOOP_%=:\n\t"
        "mbarrier.try_wait.parity.acquire.cta.shared::cta.b64 P1, [%0], %1, 0x989680;\n\t"
        "@P1 bra.uni WAIT_DONE_%=;\n\t"
        "bra.uni WAIT_LOOP_%=;\n\t"
        "WAIT_DONE_%=:\n\t"
        "}"
        :: "r"(mbar), "r"(parity) : "memory");
}
__device__ __forceinline__ void bulk_g2s(uint32_t smem_dst, const void* gsrc,
                                         uint32_t bytes, uint32_t mbar)
{
    asm volatile(
        "cp.async.bulk.shared::cluster.global.mbarrier::complete_tx::bytes "
        "[%0], [%1], %2, [%3];"
        :: "r"(smem_dst), "l"(gsrc), "r"(bytes), "r"(mbar) : "memory");
}
__device__ __forceinline__ void bulk_s2g(void* gdst, uint32_t smem_src,
                                         uint32_t bytes)
{
    asm volatile("cp.async.bulk.global.shared::cta.bulk_group [%0], [%1], %2;"
                 :: "l"(gdst), "r"(smem_src), "r"(bytes) : "memory");
    asm volatile("cp.async.bulk.commit_group;" ::: "memory");
}
__device__ __forceinline__ void bulk_store_wait1()
{
    asm volatile("cp.async.bulk.wait_group 1;" ::: "memory");
}
__device__ __forceinline__ void bulk_store_wait0()
{
    asm volatile("cp.async.bulk.wait_group 0;" ::: "memory");
}
__device__ __forceinline__ void fence_async_proxy()
{
    asm volatile("fence.proxy.async.shared::cta;" ::: "memory");
}

// ---------------------------------------------------------------------------
// Kernel 1: build SG bitmask (4 atoms/thread, MLP=4) AND zero resi+atomE.
// ---------------------------------------------------------------------------
__global__ void mask_zero_kernel(const int* __restrict__ desc,
                                 float* __restrict__ out,
                                 int n_atoms, int zero_float4s)
{
    int base = blockIdx.x * 1024;
    int an[4];
#pragma unroll
    for (int u = 0; u < 4; u++) {
        int a = base + u * 256 + threadIdx.x;
        an[u] = (a < n_atoms) ? __ldcs(desc + 4 * a) : 0;   // at_name column
    }
#pragma unroll
    for (int u = 0; u < 4; u++) {
        int a = base + u * 256 + threadIdx.x;
        unsigned ball = __ballot_sync(0xffffffffu, an[u] == SG_CODE);
        if ((threadIdx.x & 31) == 0 && a < n_atoms)
            g_sgmask[a >> 5] = ball;
    }

    float4 z = make_float4(0.f, 0.f, 0.f, 0.f);
    int stride = gridDim.x * blockDim.x;
    for (int t = blockIdx.x * blockDim.x + threadIdx.x;
         t < zero_float4s; t += stride)
        __stcs(reinterpret_cast<float4*>(out) + t, z);
}

// ---------------------------------------------------------------------------
// Heavy path (rare): one true sulfur pair -> atomE + resi atomics.
// ---------------------------------------------------------------------------
__device__ __forceinline__ void heavy_pair(int i, int j,
                                           const float* __restrict__ coords,
                                           const int4* __restrict__ desc4,
                                           const uint32_t* __restrict__ amask,
                                           float* __restrict__ atomE,
                                           float* __restrict__ resi)
{
    float dx = __ldg(coords + 3 * i + 0) - __ldg(coords + 3 * j + 0) + 1e-6f;
    float dy = __ldg(coords + 3 * i + 1) - __ldg(coords + 3 * j + 1) + 1e-6f;
    float dz = __ldg(coords + 3 * i + 2) - __ldg(coords + 3 * j + 2) + 1e-6f;
    float dist = sqrtf(dx * dx + dy * dy + dz * dz);

    int4 di = __ldg(desc4 + i);
    int4 dj = __ldg(desc4 + j);

    float rd  = fabsf((float)(di.y - dj.y));
    float rds = (rd > 0.f) ? rd : 1.0f;

    float energy = -0.298f * (2.1f + 2.9823825f * logf(rds))
                 + 5.0f * fabsf(dist - 2.04f);
    float net = 0.5f * energy;

    int flat_i = (di.z * N_CHAINS + di.w) * N_RES + di.y;
    int flat_j = (dj.z * N_CHAINS + dj.w) * N_RES + dj.y;

    uint4 mi = *reinterpret_cast<const uint4*>(amask + 4 * (size_t)i);
    uint4 mj = *reinterpret_cast<const uint4*>(amask + 4 * (size_t)j);

#define ALT(A, MI, MJ)                                                       \
    if ((MI) && (MJ)) {                                                      \
        atomicAdd(atomE + 4 * (size_t)i + (A), net);                         \
        atomicAdd(atomE + 4 * (size_t)j + (A), net);                         \
        atomicAdd(resi  + 4 * (size_t)flat_i + (A), net);                    \
        atomicAdd(resi  + 4 * (size_t)flat_j + (A), net);                    \
    }
    ALT(0, mi.x, mj.x)
    ALT(1, mi.y, mj.y)
    ALT(2, mi.z, mj.z)
    ALT(3, mi.w, mj.w)
#undef ALT
}

__device__ __noinline__ void heavy_chunk(int4 a, unsigned s0, unsigned s1,
                                         const float* __restrict__ coords,
                                         const int4* __restrict__ desc4,
                                         const uint32_t* __restrict__ amask,
                                         float* __restrict__ atomE,
                                         float* __restrict__ resi)
{
    if (s0) heavy_pair(a.x, a.y, coords, desc4, amask, atomE, resi);
    if (s1) heavy_pair(a.z, a.w, coords, desc4, amask, atomE, resi);
}

// ---------------------------------------------------------------------------
// Kernel 2: bulk-async pair sweep.
// Per CTA: mask bulk-copied once; pairs stream through 2x16KB smem tiles
// (bulk-in, issued 2 tiles ahead); sulfur written to 8KB out-tiles and
// bulk-stored. Per-thread hot work: 1 LDS.128 + 4 mask LDS + 1 STS.64.
// ---------------------------------------------------------------------------
__global__ void __launch_bounds__(PBLOCK, 2)
pair_kernel(const int4* __restrict__ pairs2,
            const float* __restrict__ coords,
            const int4* __restrict__ desc4,
            const uint32_t* __restrict__ amask,
            float* __restrict__ out,
            int n_pairs, int n_atoms, int resi_floats)
{
    extern __shared__ __align__(16) char smem[];
    uint32_t* smask = reinterpret_cast<uint32_t*>(smem);
    int4*   tin0  = reinterpret_cast<int4*>(smem + IN_OFF);
    int4*   tin1  = reinterpret_cast<int4*>(smem + IN_OFF + TILE * 16);
    float2* tout0 = reinterpret_cast<float2*>(smem + OUT_OFF);
    float2* tout1 = reinterpret_cast<float2*>(smem + OUT_OFF + TILE * 8);

    uint32_t mb_mask = smem_u32(smem + MBAR_OFF);
    uint32_t mb_in0  = mb_mask + 8;
    uint32_t mb_in1  = mb_mask + 16;

    int tid = threadIdx.x;
    int nwords = (n_atoms + 31) >> 5;
    uint32_t mask_bytes = (uint32_t)(((nwords * 4) + 15) & ~15);

    float* resi  = out;
    float* atomE = out + resi_floats;
    float* sout  = atomE + 4 * (size_t)n_atoms;

    int n2    = n_pairs >> 1;                       // int4 groups
    int tiles = (n2 + TILE - 1) / TILE;
    int g     = gridDim.x;
    int bx    = blockIdx.x;
    int nmy   = (bx < tiles) ? ((tiles - bx + g - 1) / g) : 0;

    // -- init mbarriers, then issue mask copy + first two tile loads --------
    if (tid == 0) {
        mbar_init(mb_mask, 1);
        mbar_init(mb_in0, 1);
        mbar_init(mb_in1, 1);
    }
    __syncthreads();

    if (tid == 0) {
        mbar_expect_tx(mb_mask, mask_bytes);
        bulk_g2s(smem_u32(smask), g_sgmask, mask_bytes, mb_mask);

        if (nmy > 0) {
            int t0 = bx;
            uint32_t c0 = (uint32_t)min(TILE, n2 - t0 * TILE) * 16u;
            mbar_expect_tx(mb_in0, c0);
            bulk_g2s(smem_u32(tin0), pairs2 + (size_t)t0 * TILE, c0, mb_in0);
        }
        if (nmy > 1) {
            int t1 = bx + g;
            uint32_t c1 = (uint32_t)min(TILE, n2 - t1 * TILE) * 16u;
            mbar_expect_tx(mb_in1, c1);
            bulk_g2s(smem_u32(tin1), pairs2 + (size_t)t1 * TILE, c1, mb_in1);
        }
    }

    // wait for mask before any lookup
    mbar_wait(mb_mask, 0);

    int p0 = 0, p1 = 0;                             // per-stage phase parity

    for (int k = 0; k < nmy; k++) {
        int s = k & 1;
        int tile_id = bx + k * g;
        int base = tile_id * TILE;
        int cnt = min(TILE, n2 - base);

        // wait input tile
        if (s == 0) { mbar_wait(mb_in0, p0); p0 ^= 1; }
        else        { mbar_wait(mb_in1, p1); p1 ^= 1; }

        int4* tin = s ? tin1 : tin0;
        float2* tout = s ? tout1 : tout0;

        int4 a = tin[tid];
        if (tid >= cnt) a = make_int4(0, 0, 0, 0);  // clamp (last tile only)

#define BIT(I) (smask[(unsigned)(I) >> 5] >> ((I) & 31))
        unsigned s0 = BIT(a.x) & BIT(a.y) & 1u;
        unsigned s1 = BIT(a.z) & BIT(a.w) & 1u;
#undef BIT

        // out-tile for this stage must be free (store from 2 tiles ago done)
        if (tid == 0) bulk_store_wait1();
        __syncthreads();                            // reads of tin done too

        float2 so;
        so.x = (float)s0;
        so.y = (float)s1;
        tout[tid] = so;
        __syncthreads();                            // out tile complete

        if (tid == 0) {
            fence_async_proxy();
            bulk_s2g(reinterpret_cast<float2*>(sout) + base,
                     smem_u32(tout), (uint32_t)cnt * 8u);

            // refill this stage for tile k+2
            int k2 = k + 2;
            if (k2 < nmy) {
                int t2 = bx + k2 * g;
                uint32_t c2 = (uint32_t)min(TILE, n2 - t2 * TILE) * 16u;
                uint32_t mb = s ? mb_in1 : mb_in0;
                mbar_expect_tx(mb, c2);
                bulk_g2s(smem_u32(tin), pairs2 + (size_t)t2 * TILE, c2, mb);
            }
        }

        // rare heavy path (direct gmem atomics)
        if ((s0 | s1) && tid < cnt)
            heavy_chunk(a, s0, s1, coords, desc4, amask, atomE, resi);
    }

    if (tid == 0 && nmy > 0) bulk_store_wait0();    // drain stores

    // tail: odd pair (n_pairs even here; kept general)
    if ((n_pairs & 1) && bx == 0 && tid == 0) {
        const int* pp = reinterpret_cast<const int*>(pairs2);
        int i = __ldg(pp + 2 * (n_pairs - 1));
        int j = __ldg(pp + 2 * (n_pairs - 1) + 1);
        unsigned s = (smask[i >> 5] >> (i & 31))
                   & (smask[j >> 5] >> (j & 31)) & 1u;
        sout[n_pairs - 1] = s ? 1.0f : 0.0f;
        if (s) heavy_pair(i, j, coords, desc4, amask, atomE, resi);
    }
}

// ---------------------------------------------------------------------------
extern "C" void kernel_launch(void* const* d_in, const int* in_sizes, int n_in,
                              void* d_out, int out_size)
{
    const float*    coords = (const float*)d_in[0];
    const int*      desc   = (const int*)d_in[1];
    const int*      pairs  = (const int*)d_in[2];
    const uint32_t* amask  = (const uint32_t*)d_in[3];
    float*          out    = (float*)d_out;

    int n_atoms = in_sizes[0] / 3;
    int n_pairs = in_sizes[2] / 2;
    int n_alt   = in_sizes[3] / n_atoms;                      // 4
    int resi_floats = out_size - n_atoms * n_alt - n_pairs;   // 64000

    cudaFuncSetAttribute(pair_kernel,
                         cudaFuncAttributeMaxDynamicSharedMemorySize,
                         SMEM_TOT);

    // Mask build + zero resi/atomE regions.
    int mblocks = (n_atoms + 1023) / 1024;
    int zero_float4s = (resi_floats + n_atoms * n_alt) / 4;
    mask_zero_kernel<<<mblocks, 256>>>(desc, out, n_atoms, zero_float4s);

    // 2 CTAs/SM x 1024 threads; bulk-async double-buffered pipeline.
    pair_kernel<<<296, PBLOCK, SMEM_TOT>>>((const int4*)pairs, coords,
                                           (const int4*)desc, amask,
                                           out, n_pairs, n_atoms, resi_floats);
}

// round 12
// speedup vs baseline: 1.4128x; 1.4128x over previous
#include <cuda_runtime.h>
#include <cstdint>

// DisulfideEnergy: sulfur-pair energy scatter + fused residue reduction.
//
// Output (single f32 buffer):
//   [0 .. 64000)              resi_energy (8,4,500,4)
//   [64000 .. 2064000)        atom_energy (500000,4)
//   [2064000 .. 6064000)      sulfur      (4000000) as 0.0/1.0

#define N_CHAINS   4
#define N_RES      500
#define SG_CODE    7
#define MAX_ATOMS  500000
#define MAX_WORDS  ((MAX_ATOMS + 31) / 32)   // 15625
#define PBLOCK     1024

__device__ __align__(16) uint32_t g_sgmask[MAX_WORDS + 32];

// ---------------------------------------------------------------------------
// Kernel 1: build SG bitmask (4 atoms/thread, MLP=4) AND zero resi+atomE.
// ---------------------------------------------------------------------------
__global__ void mask_zero_kernel(const int* __restrict__ desc,
                                 float* __restrict__ out,
                                 int n_atoms, int zero_float4s)
{
    int base = blockIdx.x * 1024;
    int an[4];
#pragma unroll
    for (int u = 0; u < 4; u++) {
        int a = base + u * 256 + threadIdx.x;
        an[u] = (a < n_atoms) ? __ldcs(desc + 4 * a) : 0;   // at_name column
    }
#pragma unroll
    for (int u = 0; u < 4; u++) {
        int a = base + u * 256 + threadIdx.x;
        unsigned ball = __ballot_sync(0xffffffffu, an[u] == SG_CODE);
        if ((threadIdx.x & 31) == 0 && a < n_atoms)
            g_sgmask[a >> 5] = ball;
    }

    // zero resi + atom_energy regions (grid-stride, float4)
    float4 z = make_float4(0.f, 0.f, 0.f, 0.f);
    int stride = gridDim.x * blockDim.x;
    for (int t = blockIdx.x * blockDim.x + threadIdx.x;
         t < zero_float4s; t += stride)
        __stcs(reinterpret_cast<float4*>(out) + t, z);
}

// ---------------------------------------------------------------------------
// Heavy path: one true sulfur pair. Updates atomE AND resi.
// ---------------------------------------------------------------------------
__device__ __forceinline__ void heavy_pair(int i, int j,
                                           const float* __restrict__ coords,
                                           const int4* __restrict__ desc4,
                                           const uint32_t* __restrict__ amask,
                                           float* __restrict__ atomE,
                                           float* __restrict__ resi)
{
    float dx = __ldg(coords + 3 * i + 0) - __ldg(coords + 3 * j + 0) + 1e-6f;
    float dy = __ldg(coords + 3 * i + 1) - __ldg(coords + 3 * j + 1) + 1e-6f;
    float dz = __ldg(coords + 3 * i + 2) - __ldg(coords + 3 * j + 2) + 1e-6f;
    float dist = sqrtf(dx * dx + dy * dy + dz * dz);

    int4 di = __ldg(desc4 + i);   // (at_name, resnum, batch, chain)
    int4 dj = __ldg(desc4 + j);

    float rd  = fabsf((float)(di.y - dj.y));
    float rds = (rd > 0.f) ? rd : 1.0f;

    // -0.001*298.0 = -0.298
    float energy = -0.298f * (2.1f + 2.9823825f * logf(rds))
                 + 5.0f * fabsf(dist - 2.04f);
    float net = 0.5f * energy;

    int flat_i = (di.z * N_CHAINS + di.w) * N_RES + di.y;
    int flat_j = (dj.z * N_CHAINS + dj.w) * N_RES + dj.y;

    uint4 mi = *reinterpret_cast<const uint4*>(amask + 4 * (size_t)i);
    uint4 mj = *reinterpret_cast<const uint4*>(amask + 4 * (size_t)j);

#define ALT(A, MI, MJ)                                                       \
    if ((MI) && (MJ)) {                                                      \
        atomicAdd(atomE + 4 * (size_t)i + (A), net);                         \
        atomicAdd(atomE + 4 * (size_t)j + (A), net);                         \
        atomicAdd(resi  + 4 * (size_t)flat_i + (A), net);                    \
        atomicAdd(resi  + 4 * (size_t)flat_j + (A), net);                    \
    }
    ALT(0, mi.x, mj.x)
    ALT(1, mi.y, mj.y)
    ALT(2, mi.z, mj.z)
    ALT(3, mi.w, mj.w)
#undef ALT
}

// Cold handler for 4 pairs: single branch target in the hot loop.
__device__ __noinline__ void heavy_quad(int4 a0, int4 a1,
                                        unsigned s0, unsigned s1,
                                        unsigned s2, unsigned s3,
                                        const float* __restrict__ coords,
                                        const int4* __restrict__ desc4,
                                        const uint32_t* __restrict__ amask,
                                        float* __restrict__ atomE,
                                        float* __restrict__ resi)
{
    if (s0) heavy_pair(a0.x, a0.y, coords, desc4, amask, atomE, resi);
    if (s1) heavy_pair(a0.z, a0.w, coords, desc4, amask, atomE, resi);
    if (s2) heavy_pair(a1.x, a1.y, coords, desc4, amask, atomE, resi);
    if (s3) heavy_pair(a1.z, a1.w, coords, desc4, amask, atomE, resi);
}

// ---------------------------------------------------------------------------
// Kernel 2: pair sweep — branchless, 4 pairs/iter, software-pipelined.
// 1024 thr x 2 CTAs/SM = 64 warps/SM (32 regs). Per iteration: 2 clamped
// prefetch LDG.128 (32B/thread in flight), 8 unconditional LDS lookups,
// 1 STG.128, ONE rarely-taken branch to the cold handler.
// ---------------------------------------------------------------------------
__global__ void __launch_bounds__(PBLOCK, 2)
pair_kernel(const int4* __restrict__ pairs2,
            const float* __restrict__ coords,
            const int4* __restrict__ desc4,
            const uint32_t* __restrict__ amask,
            float* __restrict__ out,
            int n_pairs, int n_atoms, int resi_floats)
{
    extern __shared__ __align__(16) uint32_t smask[];
    int nwords = (n_atoms + 31) >> 5;

    // stage mask (vectorized)
    {
        int nw4 = nwords >> 2;
        const uint4* gm4 = reinterpret_cast<const uint4*>(g_sgmask);
        uint4* sm4 = reinterpret_cast<uint4*>(smask);
        for (int w = threadIdx.x; w < nw4; w += blockDim.x)
            sm4[w] = gm4[w];
        for (int w = (nw4 << 2) + threadIdx.x; w < nwords; w += blockDim.x)
            smask[w] = g_sgmask[w];
    }
    __syncthreads();

    float* resi  = out;
    float* atomE = out + resi_floats;
    float* sout  = atomE + 4 * (size_t)n_atoms;

    int n4 = n_pairs >> 2;                     // groups of 4 pairs (2 int4)
    int stride = gridDim.x * blockDim.x;
    int idx = blockIdx.x * blockDim.x + threadIdx.x;

    if (idx < n4) {
        int4 a0 = __ldcs(pairs2 + 2 * idx);
        int4 a1 = __ldcs(pairs2 + 2 * idx + 1);

        do {
            // clamped unconditional prefetch (no guard branch)
            int nidx = idx + stride;
            int pidx = min(nidx, n4 - 1);
            int4 b0 = __ldcs(pairs2 + 2 * pidx);
            int4 b1 = __ldcs(pairs2 + 2 * pidx + 1);

            // unconditional mask lookups — pure LDS+ALU, branch-free
#define BIT(I) (smask[(unsigned)(I) >> 5] >> ((I) & 31))
            unsigned s0 = BIT(a0.x) & BIT(a0.y) & 1u;
            unsigned s1 = BIT(a0.z) & BIT(a0.w) & 1u;
            unsigned s2 = BIT(a1.x) & BIT(a1.y) & 1u;
            unsigned s3 = BIT(a1.z) & BIT(a1.w) & 1u;
#undef BIT

            float4 so;
            so.x = (float)s0;
            so.y = (float)s1;
            so.z = (float)s2;
            so.w = (float)s3;
            __stcs(reinterpret_cast<float4*>(sout) + idx, so);

            // single rarely-taken branch (p ~ 1/400 per quad)
            if (s0 | s1 | s2 | s3)
                heavy_quad(a0, a1, s0, s1, s2, s3,
                           coords, desc4, amask, atomE, resi);

            a0 = b0; a1 = b1;
            idx = nidx;
        } while (idx < n4);
    }

    // tail: n_pairs % 4 (zero here, kept general)
    if (blockIdx.x == 0 && threadIdx.x == 0) {
        const int* pp = reinterpret_cast<const int*>(pairs2);
        for (int q = n4 << 2; q < n_pairs; q++) {
            int i = pp[2 * q], j = pp[2 * q + 1];
            unsigned s = (smask[i >> 5] >> (i & 31))
                       & (smask[j >> 5] >> (j & 31)) & 1u;
            sout[q] = s ? 1.0f : 0.0f;
            if (s) heavy_pair(i, j, coords, desc4, amask, atomE, resi);
        }
    }
}

// ---------------------------------------------------------------------------
extern "C" void kernel_launch(void* const* d_in, const int* in_sizes, int n_in,
                              void* d_out, int out_size)
{
    const float*    coords = (const float*)d_in[0];
    const int*      desc   = (const int*)d_in[1];
    const int*      pairs  = (const int*)d_in[2];
    const uint32_t* amask  = (const uint32_t*)d_in[3];
    float*          out    = (float*)d_out;

    int n_atoms = in_sizes[0] / 3;
    int n_pairs = in_sizes[2] / 2;
    int n_alt   = in_sizes[3] / n_atoms;                      // 4
    int resi_floats = out_size - n_atoms * n_alt - n_pairs;   // 64000

    int nwords = (n_atoms + 31) >> 5;
    size_t smem = (size_t)((nwords + 3) & ~3) * 4;            // 62512 B

    cudaFuncSetAttribute(pair_kernel,
                         cudaFuncAttributeMaxDynamicSharedMemorySize,
                         (int)smem);

    // Mask build + zero resi/atomE regions in one kernel.
    int mblocks = (n_atoms + 1023) / 1024;
    int zero_float4s = (resi_floats + n_atoms * n_alt) / 4;
    mask_zero_kernel<<<mblocks, 256>>>(desc, out, n_atoms, zero_float4s);

    // 2 CTAs/SM x 1024 threads = 64 warps/SM.
    pair_kernel<<<296, PBLOCK, smem>>>((const int4*)pairs, coords,
                                       (const int4*)desc, amask,
                                       out, n_pairs, n_atoms, resi_floats);
}

// round 14
// speedup vs baseline: 1.6673x; 1.1801x over previous
#include <cuda_runtime.h>
#include <cstdint>

// DisulfideEnergy: sulfur-pair energy scatter + fused residue reduction.
//
// Output (single f32 buffer):
//   [0 .. 64000)              resi_energy (8,4,500,4)
//   [64000 .. 2064000)        atom_energy (500000,4)
//   [2064000 .. 6064000)      sulfur      (4000000) as 0.0/1.0

#define N_CHAINS   4
#define N_RES      500
#define SG_CODE    7
#define MAX_ATOMS  500000
#define MAX_WORDS  ((MAX_ATOMS + 31) / 32)   // 15625
#define PBLOCK     1024

__device__ __align__(16) uint32_t g_sgmask[MAX_WORDS + 32];

// ---------------------------------------------------------------------------
// Kernel 1: build SG bitmask (4 atoms/thread, MLP=4) AND zero resi+atomE.
// ---------------------------------------------------------------------------
__global__ void mask_zero_kernel(const int* __restrict__ desc,
                                 float* __restrict__ out,
                                 int n_atoms, int zero_float4s)
{
    int base = blockIdx.x * 1024;
    int an[4];
#pragma unroll
    for (int u = 0; u < 4; u++) {
        int a = base + u * 256 + threadIdx.x;
        an[u] = (a < n_atoms) ? __ldcs(desc + 4 * a) : 0;   // at_name column
    }
#pragma unroll
    for (int u = 0; u < 4; u++) {
        int a = base + u * 256 + threadIdx.x;
        unsigned ball = __ballot_sync(0xffffffffu, an[u] == SG_CODE);
        if ((threadIdx.x & 31) == 0 && a < n_atoms)
            g_sgmask[a >> 5] = ball;
    }

    // zero resi + atom_energy regions (grid-stride, float4)
    float4 z = make_float4(0.f, 0.f, 0.f, 0.f);
    int stride = gridDim.x * blockDim.x;
    for (int t = blockIdx.x * blockDim.x + threadIdx.x;
         t < zero_float4s; t += stride)
        __stcs(reinterpret_cast<float4*>(out) + t, z);
}

// ---------------------------------------------------------------------------
// Heavy path: one true sulfur pair. Updates atomE AND resi.
// ---------------------------------------------------------------------------
__device__ __forceinline__ void heavy_pair(int i, int j,
                                           const float* __restrict__ coords,
                                           const int4* __restrict__ desc4,
                                           const uint32_t* __restrict__ amask,
                                           float* __restrict__ atomE,
                                           float* __restrict__ resi)
{
    float dx = __ldg(coords + 3 * i + 0) - __ldg(coords + 3 * j + 0) + 1e-6f;
    float dy = __ldg(coords + 3 * i + 1) - __ldg(coords + 3 * j + 1) + 1e-6f;
    float dz = __ldg(coords + 3 * i + 2) - __ldg(coords + 3 * j + 2) + 1e-6f;
    float dist = sqrtf(dx * dx + dy * dy + dz * dz);

    int4 di = __ldg(desc4 + i);   // (at_name, resnum, batch, chain)
    int4 dj = __ldg(desc4 + j);

    float rd  = fabsf((float)(di.y - dj.y));
    float rds = (rd > 0.f) ? rd : 1.0f;

    // -0.001*298.0 = -0.298
    float energy = -0.298f * (2.1f + 2.9823825f * logf(rds))
                 + 5.0f * fabsf(dist - 2.04f);
    float net = 0.5f * energy;

    int flat_i = (di.z * N_CHAINS + di.w) * N_RES + di.y;
    int flat_j = (dj.z * N_CHAINS + dj.w) * N_RES + dj.y;

    uint4 mi = *reinterpret_cast<const uint4*>(amask + 4 * (size_t)i);
    uint4 mj = *reinterpret_cast<const uint4*>(amask + 4 * (size_t)j);

#define ALT(A, MI, MJ)                                                       \
    if ((MI) && (MJ)) {                                                      \
        atomicAdd(atomE + 4 * (size_t)i + (A), net);                         \
        atomicAdd(atomE + 4 * (size_t)j + (A), net);                         \
        atomicAdd(resi  + 4 * (size_t)flat_i + (A), net);                    \
        atomicAdd(resi  + 4 * (size_t)flat_j + (A), net);                    \
    }
    ALT(0, mi.x, mj.x)
    ALT(1, mi.y, mj.y)
    ALT(2, mi.z, mj.z)
    ALT(3, mi.w, mj.w)
#undef ALT
}

// Cold handler for a chunk of 2 pairs: single branch target in the hot loop.
__device__ __noinline__ void heavy_chunk(int4 a, unsigned s0, unsigned s1,
                                         const float* __restrict__ coords,
                                         const int4* __restrict__ desc4,
                                         const uint32_t* __restrict__ amask,
                                         float* __restrict__ atomE,
                                         float* __restrict__ resi)
{
    if (s0) heavy_pair(a.x, a.y, coords, desc4, amask, atomE, resi);
    if (s1) heavy_pair(a.z, a.w, coords, desc4, amask, atomE, resi);
}

// ---------------------------------------------------------------------------
// Kernel 2: pair sweep — branchless hot loop (R10 shape) with a replay-
// reducing second lookup: lanes whose i-bit is 0 read smem word 0 instead of
// a random word (SEL, no branch) -> broadcast, ~2 crossbar phases instead
// of ~4. 1024 thr x 2 CTAs/SM = 64 warps/SM (32 regs), 2 pairs/iter,
// 1-deep register prefetch.
// ---------------------------------------------------------------------------
__global__ void __launch_bounds__(PBLOCK, 2)
pair_kernel(const int4* __restrict__ pairs2,
            const float* __restrict__ coords,
            const int4* __restrict__ desc4,
            const uint32_t* __restrict__ amask,
            float* __restrict__ out,
            int n_pairs, int n_atoms, int resi_floats)
{
    extern __shared__ __align__(16) uint32_t smask[];
    int nwords = (n_atoms + 31) >> 5;

    // stage mask (vectorized)
    {
        int nw4 = nwords >> 2;
        const uint4* gm4 = reinterpret_cast<const uint4*>(g_sgmask);
        uint4* sm4 = reinterpret_cast<uint4*>(smask);
        for (int w = threadIdx.x; w < nw4; w += blockDim.x)
            sm4[w] = gm4[w];
        for (int w = (nw4 << 2) + threadIdx.x; w < nwords; w += blockDim.x)
            smask[w] = g_sgmask[w];
    }
    __syncthreads();

    float* resi  = out;
    float* atomE = out + resi_floats;
    float* sout  = atomE + 4 * (size_t)n_atoms;

    int n2 = n_pairs >> 1;                     // int4 groups (2 pairs each)
    int stride = gridDim.x * blockDim.x;
    int idx = blockIdx.x * blockDim.x + threadIdx.x;

    if (idx < n2) {
        int4 a = __ldcs(pairs2 + idx);         // first chunk

        do {
            // clamped unconditional prefetch (IMNMX, no branch)
            int nidx = idx + stride;
            int pidx = min(nidx, n2 - 1);
            int4 b = __ldcs(pairs2 + pidx);

            // lookup 1 (random); lookup 2 routed to word 0 when bit1==0
            // (broadcast for ~97.5% of lanes -> ~2 phases instead of ~4)
            unsigned bi0 = (smask[(unsigned)a.x >> 5] >> (a.x & 31)) & 1u;
            unsigned bi1 = (smask[(unsigned)a.z >> 5] >> (a.z & 31)) & 1u;

            unsigned w0 = bi0 ? ((unsigned)a.y >> 5) : 0u;   // SEL
            unsigned w1 = bi1 ? ((unsigned)a.w >> 5) : 0u;   // SEL
            unsigned s0 = bi0 & (smask[w0] >> (a.y & 31));
            unsigned s1 = bi1 & (smask[w1] >> (a.w & 31));
            s0 &= 1u;
            s1 &= 1u;

            float2 so;
            so.x = (float)s0;                  // I2F, branch-free
            so.y = (float)s1;
            __stcs(reinterpret_cast<float2*>(sout) + idx, so);

            // single rarely-taken branch (p ~ 1/800 per pair)
            if (s0 | s1)
                heavy_chunk(a, s0, s1, coords, desc4, amask, atomE, resi);

            a = b;
            idx = nidx;
        } while (idx < n2);
    }

    // tail: odd pair (zero here, kept general)
    if ((n_pairs & 1) && blockIdx.x == 0 && threadIdx.x == 0) {
        const int* pp = reinterpret_cast<const int*>(pairs2);
        int i = pp[2 * (n_pairs - 1)], j = pp[2 * (n_pairs - 1) + 1];
        unsigned s = (smask[i >> 5] >> (i & 31))
                   & (smask[j >> 5] >> (j & 31)) & 1u;
        sout[n_pairs - 1] = s ? 1.0f : 0.0f;
        if (s) heavy_pair(i, j, coords, desc4, amask, atomE, resi);
    }
}

// ---------------------------------------------------------------------------
extern "C" void kernel_launch(void* const* d_in, const int* in_sizes, int n_in,
                              void* d_out, int out_size)
{
    const float*    coords = (const float*)d_in[0];
    const int*      desc   = (const int*)d_in[1];
    const int*      pairs  = (const int*)d_in[2];
    const uint32_t* amask  = (const uint32_t*)d_in[3];
    float*          out    = (float*)d_out;

    int n_atoms = in_sizes[0] / 3;
    int n_pairs = in_sizes[2] / 2;
    int n_alt   = in_sizes[3] / n_atoms;                      // 4
    int resi_floats = out_size - n_atoms * n_alt - n_pairs;   // 64000

    int nwords = (n_atoms + 31) >> 5;
    size_t smem = (size_t)((nwords + 3) & ~3) * 4;            // 62512 B

    cudaFuncSetAttribute(pair_kernel,
                         cudaFuncAttributeMaxDynamicSharedMemorySize,
                         (int)smem);

    // Mask build + zero resi/atomE regions in one kernel.
    int mblocks = (n_atoms + 1023) / 1024;
    int zero_float4s = (resi_floats + n_atoms * n_alt) / 4;
    mask_zero_kernel<<<mblocks, 256>>>(desc, out, n_atoms, zero_float4s);

    // 2 CTAs/SM x 1024 threads = 64 warps/SM.
    pair_kernel<<<296, PBLOCK, smem>>>((const int4*)pairs, coords,
                                       (const int4*)desc, amask,
                                       out, n_pairs, n_atoms, resi_floats);
}